// round 4
// baseline (speedup 1.0000x reference)
#include <cuda_runtime.h>
#include <math.h>

// ---------------- problem constants ----------------
#define NODES   100000
#define EDGESMX 1600000
#define UNITS   256
#define TSTEPS  18
#define FIN     8
#define FT      144            // FIN * TSTEPS
#define NH      (NODES*UNITS)  // 25,600,000

// ---------------- device scratch (static, no allocs; 16B-aligned for float4 access) ----------------
__device__ __align__(16) float g_dinv[NODES];
__device__ __align__(16) float g_norm[EDGESMX];
__device__ __align__(16) float g_AX[(size_t)NODES * FT];
__device__ __align__(16) float g_H [(size_t)NH];
__device__ __align__(16) float g_Z [(size_t)NH];
__device__ __align__(16) float g_HR[(size_t)NH];
__device__ __align__(16) float g_acc[(size_t)NH];
__device__ __align__(16) float g_Bzr[264 * 512];
__device__ __align__(16) float g_Bh [264 * 256];
__device__ __align__(16) float g_czr[512];
__device__ __align__(16) float g_ch [256];
__device__ __align__(16) float g_probs[TSTEPS];
__device__ int g_is64;

// edge_index dtype is ambiguous (reference asks int64; default-JAX demotes to int32).
// Little-endian int64 values < 2^31 -> int32 view has 0 at every odd slot.
__global__ void k_detect(const int* __restrict__ ei32) {
    if (threadIdx.x == 0) {
        int is64 = 1;
        for (int i = 1; i < 64; i += 2)
            if (ei32[i] != 0) { is64 = 0; break; }
        g_is64 = is64;
    }
}

__device__ __forceinline__ int edge_at(const void* ei, long long i) {
    if (g_is64) return (int)((const long long*)ei)[i];
    return ((const int*)ei)[i];
}

// ---------------- setup kernels ----------------
__global__ void k_init(int n, int nh) {
    int i = blockIdx.x * blockDim.x + threadIdx.x;
    if (i < nh) { g_H[i] = 0.f; g_acc[i] = 0.f; }
    if (i < n)  g_dinv[i] = 1.0f;   // self-loop weight
}

__global__ void k_deg(const void* __restrict__ ei, const float* __restrict__ w, int E) {
    int e = blockIdx.x * blockDim.x + threadIdx.x;
    if (e < E) {
        int d = edge_at(ei, (long long)E + e);
        atomicAdd(&g_dinv[d], w[e]);
    }
}

__global__ void k_dinv(int n) {
    int i = blockIdx.x * blockDim.x + threadIdx.x;
    if (i < n) g_dinv[i] = rsqrtf(g_dinv[i]);   // deg >= 1 always
}

__global__ void k_norm(const void* __restrict__ ei, const float* __restrict__ w, int E) {
    int e = blockIdx.x * blockDim.x + threadIdx.x;
    if (e < E) {
        int s = edge_at(ei, e);
        int d = edge_at(ei, (long long)E + e);
        g_norm[e] = g_dinv[s] * w[e] * g_dinv[d];
    }
}

__global__ void k_axinit(const float* __restrict__ x, int n) {
    int idx = blockIdx.x * blockDim.x + threadIdx.x;      // n*36 float4 chunks
    if (idx >= n * 36) return;
    int node = idx / 36, j = idx % 36;
    float c = g_dinv[node]; c *= c;                       // self-loop norm
    const float4 xv = *reinterpret_cast<const float4*>(&x[(size_t)node * FT + j * 4]);
    float4 r = make_float4(c*xv.x, c*xv.y, c*xv.z, c*xv.w);
    *reinterpret_cast<float4*>(&g_AX[(size_t)node * FT + j * 4]) = r;
}

__global__ void k_axedge(const float* __restrict__ x, const void* __restrict__ ei, int E) {
    long long idx = (long long)blockIdx.x * blockDim.x + threadIdx.x;
    if (idx >= (long long)E * 36) return;
    int e = (int)(idx / 36), j = (int)(idx % 36);
    int s = edge_at(ei, e);
    int d = edge_at(ei, (long long)E + e);
    float c = g_norm[e];
    const float4 xv = *reinterpret_cast<const float4*>(&x[(size_t)s * FT + j * 4]);
    float* p = &g_AX[(size_t)d * FT + j * 4];
    atomicAdd(p + 0, c * xv.x);
    atomicAdd(p + 1, c * xv.y);
    atomicAdd(p + 2, c * xv.z);
    atomicAdd(p + 3, c * xv.w);
}

__global__ void k_probs(const float* __restrict__ att) {
    if (threadIdx.x == 0) {
        float mx = -1e30f;
        for (int i = 0; i < TSTEPS; i++) mx = fmaxf(mx, att[i]);
        float s = 0.f, e[TSTEPS];
        for (int i = 0; i < TSTEPS; i++) { e[i] = expf(att[i] - mx); s += e[i]; }
        float inv = 1.f / s;
        for (int i = 0; i < TSTEPS; i++) g_probs[i] = e[i] * inv;
    }
}

// Fold the gconv weights into the gate linear. Output target selected ON DEVICE
// (passing __device__ symbols as host-side kernel args was the R1 bug -> err 717).
//   which: 0 -> g_Bzr cols [0,256)   (Z gate)
//          1 -> g_Bzr cols [256,512) (R gate)
//          2 -> g_Bh                  (candidate)
__global__ void k_buildB(const float* __restrict__ Wg, const float* __restrict__ Wl,
                         const float* __restrict__ bg, const float* __restrict__ bl,
                         int which) {
    float* Bout = (which == 2) ? g_Bh : g_Bzr;
    float* cout = (which == 2) ? g_ch : g_czr;
    const int ldb    = (which == 2) ? 256 : 512;
    const int coloff = (which == 1) ? 256 : 0;

    int idx = blockIdx.x * blockDim.x + threadIdx.x;
    if (idx >= 265 * 256) return;
    int k = idx >> 8, n = idx & 255;
    if (k < 256) {
        Bout[(size_t)k * ldb + coloff + n] = Wl[(size_t)(256 + k) * 256 + n];
    } else if (k < 264) {
        int f = k - 256;
        float s = 0.f;
        for (int i = 0; i < 256; i++) s += Wg[f * 256 + i] * Wl[(size_t)i * 256 + n];
        Bout[(size_t)k * ldb + coloff + n] = s;
    } else {
        float s = bl[n];
        for (int i = 0; i < 256; i++) s += bg[i] * Wl[(size_t)i * 256 + n];
        cout[coloff + n] = s;
    }
}

// ---------------- the workhorse GEMM (128x128x8 SIMT, fused epilogues) ----------------
// modes:
//  0: [H | AX_t](Nx264) @ Bzr(264x512)+czr -> sigmoid; n<256: g_Z, n>=256: g_HR = s*H
//  1: [HR| AX_t](Nx264) @ Bh (264x256)+ch  -> tanh; GRU update g_H, g_acc += p_t*Hn
//  2: relu(g_acc) @ Bp + biasp -> relu -> g_Z
//  3: g_Z        @ Bp + biasp -> relu -> g_HR
//  4: g_HR       @ Bp + biasp -> relu -> g_Z
#define BM 128
#define BN 128
#define BK 8

__global__ __launch_bounds__(256)
void gemm_kernel(const float* __restrict__ Bp, const float* __restrict__ biasp,
                 int M, int N, int mode, int t) {
    const float* A = (mode == 0) ? g_H : (mode == 1) ? g_HR
                   : (mode == 2) ? g_acc : (mode == 3) ? g_Z : g_HR;
    const float* B = (mode == 0) ? g_Bzr : (mode == 1) ? g_Bh : Bp;
    const float* bias = (mode == 0) ? g_czr : (mode == 1) ? g_ch : biasp;
    const bool useAX = (mode <= 1);
    const bool reluA = (mode == 2);

    __shared__ float As[BK][BM];
    __shared__ float Bs[BK][BN];

    int tid = threadIdx.x;
    int bm = blockIdx.x * BM;
    int bn = blockIdx.y * BN;

    int aRow = tid >> 1;           // 0..127
    int aCol = (tid & 1) * 4;      // 0 or 4
    int bRow = tid >> 5;           // 0..7
    int bCol = (tid & 31) << 2;    // 0..124

    int tr = (tid >> 4) << 3;      // 0..120
    int tc = (tid & 15) << 3;      // 0..120

    float acc[8][8];
#pragma unroll
    for (int i = 0; i < 8; i++)
#pragma unroll
        for (int j = 0; j < 8; j++) acc[i][j] = 0.f;

    const int numTiles = 32 + (useAX ? 1 : 0);
    int m = bm + aRow;
    for (int kt = 0; kt < numTiles; ++kt) {
        int k0 = kt * BK;
        if (kt < 32) {
            float4 v = make_float4(0.f, 0.f, 0.f, 0.f);
            if (m < M) v = *reinterpret_cast<const float4*>(&A[(size_t)m * 256 + k0 + aCol]);
            if (reluA) { v.x = fmaxf(v.x, 0.f); v.y = fmaxf(v.y, 0.f);
                         v.z = fmaxf(v.z, 0.f); v.w = fmaxf(v.w, 0.f); }
            As[aCol + 0][aRow] = v.x; As[aCol + 1][aRow] = v.y;
            As[aCol + 2][aRow] = v.z; As[aCol + 3][aRow] = v.w;
        } else {
#pragma unroll
            for (int i = 0; i < 4; i++) {
                int f = aCol + i;
                float v = 0.f;
                if (m < M) v = g_AX[(size_t)m * FT + f * TSTEPS + t];
                As[f][aRow] = v;
            }
        }
        float4 bv = *reinterpret_cast<const float4*>(&B[(size_t)(k0 + bRow) * N + bn + bCol]);
        *reinterpret_cast<float4*>(&Bs[bRow][bCol]) = bv;
        __syncthreads();

#pragma unroll
        for (int k = 0; k < BK; k++) {
            float4 a0 = *reinterpret_cast<const float4*>(&As[k][tr]);
            float4 a1 = *reinterpret_cast<const float4*>(&As[k][tr + 4]);
            float4 b0 = *reinterpret_cast<const float4*>(&Bs[k][tc]);
            float4 b1 = *reinterpret_cast<const float4*>(&Bs[k][tc + 4]);
            float ra[8] = {a0.x, a0.y, a0.z, a0.w, a1.x, a1.y, a1.z, a1.w};
            float rb[8] = {b0.x, b0.y, b0.z, b0.w, b1.x, b1.y, b1.z, b1.w};
#pragma unroll
            for (int i = 0; i < 8; i++)
#pragma unroll
                for (int j = 0; j < 8; j++) acc[i][j] += ra[i] * rb[j];
        }
        __syncthreads();
    }

    // fused epilogues
    float pt = (mode == 1) ? g_probs[t] : 0.f;
#pragma unroll
    for (int i = 0; i < 8; i++) {
        int mm = bm + tr + i;
        if (mm >= M) continue;
        size_t base = (size_t)mm * 256;
#pragma unroll
        for (int j = 0; j < 8; j++) {
            int n = bn + tc + j;
            float v = acc[i][j] + bias[n];
            if (mode == 0) {
                float s = 1.f / (1.f + expf(-v));
                if (n < 256) g_Z[base + n] = s;
                else { int n2 = n - 256; g_HR[base + n2] = s * g_H[base + n2]; }
            } else if (mode == 1) {
                float ht = tanhf(v);
                float z  = g_Z[base + n];
                float h  = g_H[base + n];
                float hn = z * h + (1.f - z) * ht;
                g_H[base + n] = hn;
                g_acc[base + n] += pt * hn;
            } else {
                float r = fmaxf(v, 0.f);
                if (mode == 3) g_HR[base + n] = r;
                else           g_Z [base + n] = r;
            }
        }
    }
}

// ---------------- final projection: h3(Nx256) @ Wo(256x18) + bo ----------------
__global__ void k_out(const float* __restrict__ Wo, const float* __restrict__ bo,
                      float* __restrict__ out, int M) {
    int warp = (blockIdx.x * blockDim.x + threadIdx.x) >> 5;
    int lane = threadIdx.x & 31;
    if (warp >= M) return;
    float acc[TSTEPS];
#pragma unroll
    for (int j = 0; j < TSTEPS; j++) acc[j] = 0.f;
    const float* a = g_Z + (size_t)warp * 256;
    for (int k = lane; k < 256; k += 32) {
        float av = a[k];
        const float* wr = Wo + k * TSTEPS;
#pragma unroll
        for (int j = 0; j < TSTEPS; j++) acc[j] += av * wr[j];
    }
#pragma unroll
    for (int off = 16; off > 0; off >>= 1)
#pragma unroll
        for (int j = 0; j < TSTEPS; j++)
            acc[j] += __shfl_xor_sync(0xffffffffu, acc[j], off);
    if (lane == 0) {
        float* o = out + (size_t)warp * TSTEPS;
#pragma unroll
        for (int j = 0; j < TSTEPS; j++) o[j] = acc[j] + bo[j];
    }
}

// ---------------- launch ----------------
extern "C" void kernel_launch(void* const* d_in, const int* in_sizes, int n_in,
                              void* d_out, int out_size) {
    const float* x   = (const float*)d_in[0];
    const void*  ei  = d_in[1];                 // int32 or int64 -- detected on device
    const float* w   = (const float*)d_in[2];
    const float *Wz = (const float*)d_in[3],  *bz = (const float*)d_in[4];
    const float *Wlz= (const float*)d_in[5],  *blz= (const float*)d_in[6];
    const float *Wr = (const float*)d_in[7],  *br = (const float*)d_in[8];
    const float *Wlr= (const float*)d_in[9],  *blr= (const float*)d_in[10];
    const float *Wh = (const float*)d_in[11], *bh = (const float*)d_in[12];
    const float *Wlh= (const float*)d_in[13], *blh= (const float*)d_in[14];
    const float *att= (const float*)d_in[15];
    const float *W1 = (const float*)d_in[16], *b1 = (const float*)d_in[17];
    const float *W2 = (const float*)d_in[18], *b2 = (const float*)d_in[19];
    const float *W3 = (const float*)d_in[20], *b3 = (const float*)d_in[21];
    const float *Wo = (const float*)d_in[22], *bo = (const float*)d_in[23];
    float* out = (float*)d_out;

    const int E = in_sizes[2];
    const int N = in_sizes[0] / FT;
    const int nh = N * UNITS;

    // dtype probe for edge_index
    k_detect<<<1, 32>>>((const int*)ei);

    // graph normalization + one-time feature aggregation AX = Ahat @ X  (all 144 feats)
    k_init<<<(nh + 255) / 256, 256>>>(N, nh);
    k_deg <<<(E + 255) / 256, 256>>>(ei, w, E);
    k_dinv<<<(N + 255) / 256, 256>>>(N);
    k_norm<<<(E + 255) / 256, 256>>>(ei, w, E);
    k_axinit<<<(N * 36 + 255) / 256, 256>>>(x, N);
    {
        long long tot = (long long)E * 36;
        k_axedge<<<(unsigned)((tot + 255) / 256), 256>>>(x, ei, E);
    }
    k_probs<<<1, 32>>>(att);

    // fold gconv weights into gate linears (device-side output selection)
    const int bb = (265 * 256 + 255) / 256;
    k_buildB<<<bb, 256>>>(Wz, Wlz, bz, blz, 0);
    k_buildB<<<bb, 256>>>(Wr, Wlr, br, blr, 1);
    k_buildB<<<bb, 256>>>(Wh, Wlh, bh, blh, 2);

    // recurrent steps
    const int gbm = (N + BM - 1) / BM;
    for (int t = 0; t < TSTEPS; t++) {
        gemm_kernel<<<dim3(gbm, 4), 256>>>(nullptr, nullptr, N, 512, 0, t);
        gemm_kernel<<<dim3(gbm, 2), 256>>>(nullptr, nullptr, N, 256, 1, t);
    }

    // MLP head
    gemm_kernel<<<dim3(gbm, 2), 256>>>(W1, b1, N, 256, 2, 0);
    gemm_kernel<<<dim3(gbm, 2), 256>>>(W2, b2, N, 256, 3, 0);
    gemm_kernel<<<dim3(gbm, 2), 256>>>(W3, b3, N, 256, 4, 0);

    k_out<<<(N * 32 + 255) / 256, 256>>>(Wo, bo, out, N);
}

// round 5
// speedup vs baseline: 1.8289x; 1.8289x over previous
#include <cuda_runtime.h>
#include <math.h>
#include <stdint.h>

// ---------------- problem constants ----------------
#define NODES   100000
#define EDGESMX 1600000
#define UNITS   256
#define TSTEPS  18
#define FIN     8
#define FT      144            // FIN * TSTEPS
#define NH      (NODES*UNITS)  // 25,600,000
#define KB      272            // 264 folded K rows zero-extended to 17*16

// ---------------- device scratch (static, no allocs; 16B-aligned) ----------------
__device__ __align__(16) float g_dinv[NODES];
__device__ __align__(16) float g_norm[EDGESMX];
__device__ __align__(16) float g_AX[(size_t)NODES * FT];
__device__ __align__(16) float g_H [(size_t)NH];
__device__ __align__(16) float g_Z [(size_t)NH];
__device__ __align__(16) float g_HR[(size_t)NH];
__device__ __align__(16) float g_acc[(size_t)NH];
__device__ __align__(16) float g_Bzr[KB * 512];
__device__ __align__(16) float g_Bh [KB * 256];
__device__ __align__(16) float g_czr[512];
__device__ __align__(16) float g_ch [256];
__device__ __align__(16) float g_probs[TSTEPS];
__device__ int g_is64;

// edge_index dtype probe (int64 little-endian < 2^31 -> odd int32 slots are 0)
__global__ void k_detect(const int* __restrict__ ei32) {
    if (threadIdx.x == 0) {
        int is64 = 1;
        for (int i = 1; i < 64; i += 2)
            if (ei32[i] != 0) { is64 = 0; break; }
        g_is64 = is64;
    }
}

__device__ __forceinline__ int edge_at(const void* ei, long long i) {
    if (g_is64) return (int)((const long long*)ei)[i];
    return ((const int*)ei)[i];
}

// ---------------- setup kernels ----------------
__global__ void k_init(int n, int nh) {
    int i = blockIdx.x * blockDim.x + threadIdx.x;
    if (i < nh) { g_H[i] = 0.f; g_acc[i] = 0.f; }
    if (i < n)  g_dinv[i] = 1.0f;
}

__global__ void k_deg(const void* __restrict__ ei, const float* __restrict__ w, int E) {
    int e = blockIdx.x * blockDim.x + threadIdx.x;
    if (e < E) atomicAdd(&g_dinv[edge_at(ei, (long long)E + e)], w[e]);
}

__global__ void k_dinv(int n) {
    int i = blockIdx.x * blockDim.x + threadIdx.x;
    if (i < n) g_dinv[i] = rsqrtf(g_dinv[i]);
}

__global__ void k_norm(const void* __restrict__ ei, const float* __restrict__ w, int E) {
    int e = blockIdx.x * blockDim.x + threadIdx.x;
    if (e < E) {
        int s = edge_at(ei, e);
        int d = edge_at(ei, (long long)E + e);
        g_norm[e] = g_dinv[s] * w[e] * g_dinv[d];
    }
}

__global__ void k_axinit(const float* __restrict__ x, int n) {
    int idx = blockIdx.x * blockDim.x + threadIdx.x;
    if (idx >= n * 36) return;
    int node = idx / 36, j = idx % 36;
    float c = g_dinv[node]; c *= c;
    const float4 xv = *reinterpret_cast<const float4*>(&x[(size_t)node * FT + j * 4]);
    float4 r = make_float4(c*xv.x, c*xv.y, c*xv.z, c*xv.w);
    *reinterpret_cast<float4*>(&g_AX[(size_t)node * FT + j * 4]) = r;
}

__global__ void k_axedge(const float* __restrict__ x, const void* __restrict__ ei, int E) {
    long long idx = (long long)blockIdx.x * blockDim.x + threadIdx.x;
    if (idx >= (long long)E * 36) return;
    int e = (int)(idx / 36), j = (int)(idx % 36);
    int s = edge_at(ei, e);
    int d = edge_at(ei, (long long)E + e);
    float c = g_norm[e];
    const float4 xv = *reinterpret_cast<const float4*>(&x[(size_t)s * FT + j * 4]);
    float* p = &g_AX[(size_t)d * FT + j * 4];
    atomicAdd(p + 0, c * xv.x);
    atomicAdd(p + 1, c * xv.y);
    atomicAdd(p + 2, c * xv.z);
    atomicAdd(p + 3, c * xv.w);
}

__global__ void k_probs(const float* __restrict__ att) {
    if (threadIdx.x == 0) {
        float mx = -1e30f;
        for (int i = 0; i < TSTEPS; i++) mx = fmaxf(mx, att[i]);
        float s = 0.f, e[TSTEPS];
        for (int i = 0; i < TSTEPS; i++) { e[i] = expf(att[i] - mx); s += e[i]; }
        float inv = 1.f / s;
        for (int i = 0; i < TSTEPS; i++) g_probs[i] = e[i] * inv;
    }
}

// Fold gconv into gate linear; zero-extend K rows 264..271; output selected on device.
__global__ void k_buildB(const float* __restrict__ Wg, const float* __restrict__ Wl,
                         const float* __restrict__ bg, const float* __restrict__ bl,
                         int which) {
    float* Bout = (which == 2) ? g_Bh : g_Bzr;
    float* cout = (which == 2) ? g_ch : g_czr;
    const int ldb    = (which == 2) ? 256 : 512;
    const int coloff = (which == 1) ? 256 : 0;

    int idx = blockIdx.x * blockDim.x + threadIdx.x;
    if (idx >= 273 * 256) return;
    int k = idx >> 8, n = idx & 255;
    if (k < 256) {
        Bout[(size_t)k * ldb + coloff + n] = Wl[(size_t)(256 + k) * 256 + n];
    } else if (k < 264) {
        int f = k - 256;
        float s = 0.f;
        for (int i = 0; i < 256; i++) s += Wg[f * 256 + i] * Wl[(size_t)i * 256 + n];
        Bout[(size_t)k * ldb + coloff + n] = s;
    } else if (k < KB) {
        Bout[(size_t)k * ldb + coloff + n] = 0.f;
    } else {
        float s = bl[n];
        for (int i = 0; i < 256; i++) s += bg[i] * Wl[(size_t)i * 256 + n];
        cout[coloff + n] = s;
    }
}

// ---------------- tf32 tensor-core GEMM with fused epilogues ----------------
// modes:
//  0: [H | AX_t](Nx264) @ Bzr + czr -> sigmoid; n<256: g_Z, n>=256: g_HR = s*H
//  1: [HR| AX_t](Nx264) @ Bh  + ch  -> tanh; GRU update g_H, g_acc += p_t*Hn
//  2: relu(g_acc) @ Bp + biasp -> relu -> g_Z
//  3: g_Z         @ Bp + biasp -> relu -> g_HR
//  4: g_HR        @ Bp + biasp -> relu -> g_Z
#define BMt 128
#define BNt 128
#define BKt 16
#define AS_LD (BMt + 4)
#define BS_LD (BNt + 4)

__device__ __forceinline__ uint32_t f2tf(float f) {
    uint32_t r; asm("cvt.rna.tf32.f32 %0, %1;" : "=r"(r) : "f"(f)); return r;
}

__device__ __forceinline__ void mma_tf32(float c[4], const uint32_t a[4], const uint32_t b[2]) {
    asm volatile(
        "mma.sync.aligned.m16n8k8.row.col.f32.tf32.tf32.f32 "
        "{%0,%1,%2,%3}, {%4,%5,%6,%7}, {%8,%9}, {%0,%1,%2,%3};\n"
        : "+f"(c[0]), "+f"(c[1]), "+f"(c[2]), "+f"(c[3])
        : "r"(a[0]), "r"(a[1]), "r"(a[2]), "r"(a[3]), "r"(b[0]), "r"(b[1]));
}

__global__ __launch_bounds__(256, 2)
void gemm_tc(const float* __restrict__ Bp, const float* __restrict__ biasp,
             int M, int N, int mode, int t) {
    const float* A = (mode == 0) ? g_H : (mode == 1) ? g_HR
                   : (mode == 2) ? g_acc : (mode == 3) ? g_Z : g_HR;
    const float* B = (mode == 0) ? g_Bzr : (mode == 1) ? g_Bh : Bp;
    const float* bias = (mode == 0) ? g_czr : (mode == 1) ? g_ch : biasp;
    const bool useAX = (mode <= 1);
    const bool reluA = (mode == 2);

    __shared__ uint32_t As[BKt][AS_LD];
    __shared__ uint32_t Bs[BKt][BS_LD];

    const int tid = threadIdx.x, lane = tid & 31, wid = tid >> 5;
    const int wm = (wid & 1) * 64;        // warp M origin in tile
    const int wn = (wid >> 1) * 32;       // warp N origin in tile
    const int g = lane >> 2, tg = lane & 3;
    const int bm = blockIdx.x * BMt, bn = blockIdx.y * BNt;

    const int aRow = tid >> 1, aCol = (tid & 1) * 4;   // A: 128 rows x 16 k (2 f4 each)
    const int bRow = wid, bCol = lane * 4;             // B: 16 rows x 128 n (2 f4 each)

    float c[4][4][4];
#pragma unroll
    for (int i = 0; i < 4; i++)
#pragma unroll
        for (int j = 0; j < 4; j++)
#pragma unroll
            for (int q = 0; q < 4; q++) c[i][j][q] = 0.f;

    const int nT = useAX ? 17 : 16;
    const int m = bm + aRow;

    for (int kt = 0; kt < nT; kt++) {
        const int k0 = kt * BKt;
        // ---- stage A tile (k-major, tf32) ----
        if (kt < 16) {
            float4 v0 = make_float4(0.f,0.f,0.f,0.f), v1 = v0;
            if (m < M) {
                v0 = *reinterpret_cast<const float4*>(&A[(size_t)m * 256 + k0 + aCol]);
                v1 = *reinterpret_cast<const float4*>(&A[(size_t)m * 256 + k0 + aCol + 8]);
            }
            if (reluA) {
                v0.x = fmaxf(v0.x, 0.f); v0.y = fmaxf(v0.y, 0.f);
                v0.z = fmaxf(v0.z, 0.f); v0.w = fmaxf(v0.w, 0.f);
                v1.x = fmaxf(v1.x, 0.f); v1.y = fmaxf(v1.y, 0.f);
                v1.z = fmaxf(v1.z, 0.f); v1.w = fmaxf(v1.w, 0.f);
            }
            As[aCol + 0][aRow] = f2tf(v0.x); As[aCol + 1][aRow] = f2tf(v0.y);
            As[aCol + 2][aRow] = f2tf(v0.z); As[aCol + 3][aRow] = f2tf(v0.w);
            As[aCol + 8][aRow] = f2tf(v1.x); As[aCol + 9][aRow] = f2tf(v1.y);
            As[aCol +10][aRow] = f2tf(v1.z); As[aCol +11][aRow] = f2tf(v1.w);
        } else {
            // AX tile: k rows 0..7 = AX features, 8..15 = zero
#pragma unroll
            for (int i = 0; i < 4; i++) {
                float v = 0.f;
                if (m < M) v = g_AX[(size_t)m * FT + (aCol + i) * TSTEPS + t];
                As[aCol + i][aRow] = f2tf(v);
                As[aCol + 8 + i][aRow] = 0u;
            }
        }
        // ---- stage B tile ----
        {
            float4 u0 = *reinterpret_cast<const float4*>(&B[(size_t)(k0 + bRow) * N + bn + bCol]);
            float4 u1 = *reinterpret_cast<const float4*>(&B[(size_t)(k0 + bRow + 8) * N + bn + bCol]);
            Bs[bRow][bCol + 0] = f2tf(u0.x); Bs[bRow][bCol + 1] = f2tf(u0.y);
            Bs[bRow][bCol + 2] = f2tf(u0.z); Bs[bRow][bCol + 3] = f2tf(u0.w);
            Bs[bRow + 8][bCol + 0] = f2tf(u1.x); Bs[bRow + 8][bCol + 1] = f2tf(u1.y);
            Bs[bRow + 8][bCol + 2] = f2tf(u1.z); Bs[bRow + 8][bCol + 3] = f2tf(u1.w);
        }
        __syncthreads();

#pragma unroll
        for (int kk = 0; kk < BKt; kk += 8) {
            uint32_t af[4][4], bf[4][2];
#pragma unroll
            for (int mi = 0; mi < 4; mi++) {
                int m0 = wm + mi * 16;
                af[mi][0] = As[kk + tg    ][m0 + g];
                af[mi][1] = As[kk + tg    ][m0 + g + 8];
                af[mi][2] = As[kk + tg + 4][m0 + g];
                af[mi][3] = As[kk + tg + 4][m0 + g + 8];
            }
#pragma unroll
            for (int ni = 0; ni < 4; ni++) {
                int n0 = wn + ni * 8;
                bf[ni][0] = Bs[kk + tg    ][n0 + g];
                bf[ni][1] = Bs[kk + tg + 4][n0 + g];
            }
#pragma unroll
            for (int mi = 0; mi < 4; mi++)
#pragma unroll
                for (int ni = 0; ni < 4; ni++)
                    mma_tf32(c[mi][ni], af[mi], bf[ni]);
        }
        __syncthreads();
    }

    // ---- fused epilogue ----
    const float pt = (mode == 1) ? g_probs[t] : 0.f;
#pragma unroll
    for (int mi = 0; mi < 4; mi++) {
        int r0 = bm + wm + mi * 16 + g;
#pragma unroll
        for (int half = 0; half < 2; half++) {
            int r = r0 + half * 8;
            if (r >= M) continue;
            size_t base = (size_t)r * 256;
#pragma unroll
            for (int ni = 0; ni < 4; ni++) {
                int n = bn + wn + ni * 8 + tg * 2;
                float v0 = c[mi][ni][half * 2 + 0] + bias[n];
                float v1 = c[mi][ni][half * 2 + 1] + bias[n + 1];
                if (mode == 0) {
                    float s0 = 1.f / (1.f + expf(-v0));
                    float s1 = 1.f / (1.f + expf(-v1));
                    if (n < 256) {
                        g_Z[base + n] = s0; g_Z[base + n + 1] = s1;
                    } else {
                        int n2 = n - 256;
                        g_HR[base + n2]     = s0 * g_H[base + n2];
                        g_HR[base + n2 + 1] = s1 * g_H[base + n2 + 1];
                    }
                } else if (mode == 1) {
                    float h0 = tanhf(v0), h1 = tanhf(v1);
                    float z0 = g_Z[base + n], z1 = g_Z[base + n + 1];
                    float o0 = g_H[base + n], o1 = g_H[base + n + 1];
                    float hn0 = z0 * o0 + (1.f - z0) * h0;
                    float hn1 = z1 * o1 + (1.f - z1) * h1;
                    g_H[base + n] = hn0; g_H[base + n + 1] = hn1;
                    g_acc[base + n]     += pt * hn0;
                    g_acc[base + n + 1] += pt * hn1;
                } else {
                    float r0v = fmaxf(v0, 0.f), r1v = fmaxf(v1, 0.f);
                    if (mode == 3) { g_HR[base + n] = r0v; g_HR[base + n + 1] = r1v; }
                    else           { g_Z [base + n] = r0v; g_Z [base + n + 1] = r1v; }
                }
            }
        }
    }
}

// ---------------- final projection: h3(Nx256) @ Wo(256x18) + bo ----------------
__global__ void k_out(const float* __restrict__ Wo, const float* __restrict__ bo,
                      float* __restrict__ out, int M) {
    int warp = (blockIdx.x * blockDim.x + threadIdx.x) >> 5;
    int lane = threadIdx.x & 31;
    if (warp >= M) return;
    float acc[TSTEPS];
#pragma unroll
    for (int j = 0; j < TSTEPS; j++) acc[j] = 0.f;
    const float* a = g_Z + (size_t)warp * 256;
    for (int k = lane; k < 256; k += 32) {
        float av = a[k];
        const float* wr = Wo + k * TSTEPS;
#pragma unroll
        for (int j = 0; j < TSTEPS; j++) acc[j] += av * wr[j];
    }
#pragma unroll
    for (int off = 16; off > 0; off >>= 1)
#pragma unroll
        for (int j = 0; j < TSTEPS; j++)
            acc[j] += __shfl_xor_sync(0xffffffffu, acc[j], off);
    if (lane == 0) {
        float* o = out + (size_t)warp * TSTEPS;
#pragma unroll
        for (int j = 0; j < TSTEPS; j++) o[j] = acc[j] + bo[j];
    }
}

// ---------------- launch ----------------
extern "C" void kernel_launch(void* const* d_in, const int* in_sizes, int n_in,
                              void* d_out, int out_size) {
    const float* x   = (const float*)d_in[0];
    const void*  ei  = d_in[1];
    const float* w   = (const float*)d_in[2];
    const float *Wz = (const float*)d_in[3],  *bz = (const float*)d_in[4];
    const float *Wlz= (const float*)d_in[5],  *blz= (const float*)d_in[6];
    const float *Wr = (const float*)d_in[7],  *br = (const float*)d_in[8];
    const float *Wlr= (const float*)d_in[9],  *blr= (const float*)d_in[10];
    const float *Wh = (const float*)d_in[11], *bh = (const float*)d_in[12];
    const float *Wlh= (const float*)d_in[13], *blh= (const float*)d_in[14];
    const float *att= (const float*)d_in[15];
    const float *W1 = (const float*)d_in[16], *b1 = (const float*)d_in[17];
    const float *W2 = (const float*)d_in[18], *b2 = (const float*)d_in[19];
    const float *W3 = (const float*)d_in[20], *b3 = (const float*)d_in[21];
    const float *Wo = (const float*)d_in[22], *bo = (const float*)d_in[23];
    float* out = (float*)d_out;

    const int E = in_sizes[2];
    const int N = in_sizes[0] / FT;
    const int nh = N * UNITS;

    k_detect<<<1, 32>>>((const int*)ei);

    k_init<<<(nh + 255) / 256, 256>>>(N, nh);
    k_deg <<<(E + 255) / 256, 256>>>(ei, w, E);
    k_dinv<<<(N + 255) / 256, 256>>>(N);
    k_norm<<<(E + 255) / 256, 256>>>(ei, w, E);
    k_axinit<<<(N * 36 + 255) / 256, 256>>>(x, N);
    {
        long long tot = (long long)E * 36;
        k_axedge<<<(unsigned)((tot + 255) / 256), 256>>>(x, ei, E);
    }
    k_probs<<<1, 32>>>(att);

    const int bb = (273 * 256 + 255) / 256;
    k_buildB<<<bb, 256>>>(Wz, Wlz, bz, blz, 0);
    k_buildB<<<bb, 256>>>(Wr, Wlr, br, blr, 1);
    k_buildB<<<bb, 256>>>(Wh, Wlh, bh, blh, 2);

    const int gbm = (N + BMt - 1) / BMt;
    for (int t = 0; t < TSTEPS; t++) {
        gemm_tc<<<dim3(gbm, 4), 256>>>(nullptr, nullptr, N, 512, 0, t);
        gemm_tc<<<dim3(gbm, 2), 256>>>(nullptr, nullptr, N, 256, 1, t);
    }

    gemm_tc<<<dim3(gbm, 2), 256>>>(W1, b1, N, 256, 2, 0);
    gemm_tc<<<dim3(gbm, 2), 256>>>(W2, b2, N, 256, 3, 0);
    gemm_tc<<<dim3(gbm, 2), 256>>>(W3, b3, N, 256, 4, 0);

    k_out<<<(N * 32 + 255) / 256, 256>>>(Wo, bo, out, N);
}